// round 15
// baseline (speedup 1.0000x reference)
#include <cuda_runtime.h>
#include <cuda_bf16.h>
#include <math.h>
#include <stdint.h>
#include <stddef.h>

#define BB   2
#define N0   4096
#define N1   1024
#define N2   256
#define KNN  20
#define AA   12

#define C0   32
#define C1   64
#define C2   128
#define C3   256
#define C4   512

#define NSLICE 256

// KNN parallelization
#define KT    8          // threads per query
#define QB    32         // queries per block (KT*QB = 256 threads)
#define KTILE 256

#define INF_F __int_as_float(0x7f800000)

// ---------------- scratch (device globals; no runtime allocation) ----------------
// All feature maps use layout (node, a, c): element (node, a, c) at node*AA*C + a*C + c.
__device__ float d_fm0 [BB*N0*C0*AA];
__device__ float d_fm1 [BB*N0*C1*AA];
__device__ float d_fmp1[BB*N1*C1*AA];
__device__ float d_fm2 [BB*N1*C2*AA];
__device__ float d_fm3 [BB*N1*C3*AA];
__device__ float d_fmp2[BB*N2*C3*AA];
__device__ float d_fm4 [BB*N2*C4*AA];
__device__ float d_gbuf [BB*N0*C1*AA];
__device__ float d_fcbuf[BB*N0*C1*AA];
__device__ int   d_idx0[BB*N0*KNN];
__device__ int   d_idx1[BB*N1*KNN];
__device__ int   d_idx2[BB*N2*KNN];
__device__ float d_v1[BB*N1*3];
__device__ float d_v2[BB*N2*3];
__device__ float d_bnscale[C4];
__device__ float d_bnshift[C4];
__device__ double d_bnpart[NSLICE*C3*2];

// ---------------- packed fp32x2 helpers ----------------
__device__ __forceinline__ unsigned long long pack2(float lo, float hi) {
    unsigned long long r;
    asm("mov.b64 %0, {%1, %2};" : "=l"(r) : "f"(lo), "f"(hi));
    return r;
}
__device__ __forceinline__ unsigned long long fma2(unsigned long long a,
                                                   unsigned long long b,
                                                   unsigned long long c) {
    unsigned long long d;
    asm("fma.rn.f32x2 %0, %1, %2, %3;" : "=l"(d) : "l"(a), "l"(b), "l"(c));
    return d;
}

// ---------------- KNN: 8 threads/query, register top-21, shared pruning bound, 8-way merge ----
// Distance identical to reference: (d2_q + d2_j) - 2*dot.
// qbnd[ql] = min over threads of a thread's 21st-best (positive-only atomicMin on float bits):
// any dist >= qbnd cannot be in the GLOBAL top-21 (that one thread already holds 21 better),
// so pruning with it cannot change the merged result. Merge picks lexicographic (dist, idx)
// min -> exact single-scan result.
__global__ void __launch_bounds__(256)
knn_kernel(const float* __restrict__ v, int* __restrict__ idx, int npts) {
    int b = blockIdx.y;
    int tid = threadIdx.x;
    int sub = tid % KT;
    int ql  = tid / KT;
    int q = blockIdx.x * QB + ql;
    const float* vb = v + (size_t)b * npts * 3;

    float qx = vb[q*3+0], qy = vb[q*3+1], qz = vb[q*3+2];
    float qd2 = qx*qx + qy*qy + qz*qz;

    float bd[KNN+1];
    int   bi[KNN+1];
#pragma unroll
    for (int i = 0; i <= KNN; i++) { bd[i] = INF_F; bi[i] = -1; }

    __shared__ float sx[KTILE], sy[KTILE], sz[KTILE], sd2[KTILE];
    __shared__ int   qbnd[QB];
    __shared__ float msd[QB][KT][KNN+1];
    __shared__ int   msi[QB][KT][KNN+1];

    if (tid < QB) qbnd[tid] = 0x7f800000;   // +inf bits

    for (int tile = 0; tile < npts; tile += KTILE) {
        int j = tile + tid;
        if (j < npts) {
            float x = vb[j*3+0], y = vb[j*3+1], z = vb[j*3+2];
            sx[tid] = x; sy[tid] = y; sz[tid] = z;
            sd2[tid] = x*x + y*y + z*z;
        }
        __syncthreads();
        int cnt = npts - tile; if (cnt > KTILE) cnt = KTILE;
        float qb = __int_as_float(qbnd[ql]);            // per-tile snapshot (conservative)
        float bound = fminf(bd[KNN], qb);
        for (int jj = sub; jj < cnt; jj += KT) {
            float dot  = qx*sx[jj] + qy*sy[jj] + qz*sz[jj];
            float dist = (qd2 + sd2[jj]) - 2.0f*dot;
            if (dist < bound) {
                int jidx = tile + jj;
                // branchless register insertion, descending slots
#pragma unroll
                for (int i = KNN; i > 0; i--) {
                    bool up = bd[i-1] > dist;
                    bool pl = bd[i]   > dist;
                    float nb = up ? bd[i-1] : (pl ? dist : bd[i]);
                    int   ni = up ? bi[i-1] : (pl ? jidx : bi[i]);
                    bd[i] = nb; bi[i] = ni;
                }
                if (bd[0] > dist) { bd[0] = dist; bi[0] = jidx; }
                bound = fminf(bd[KNN], qb);
            }
        }
        // publish tightened bound (positive floats compare correctly as ints;
        // skipping negatives keeps the bound conservative -> still exact)
        float w = bd[KNN];
        if (w < qb && w >= 0.0f && w < INF_F)
            atomicMin(&qbnd[ql], __float_as_int(w));
        __syncthreads();
    }

    // dump per-thread lists
#pragma unroll
    for (int i = 0; i <= KNN; i++) { msd[ql][sub][i] = bd[i]; msi[ql][sub][i] = bi[i]; }
    __syncthreads();

    // one thread per query: 8-way merge of sorted lists, drop first (self)
    if (tid < QB) {
        int qq = blockIdx.x * QB + tid;
        int ptr[KT];
#pragma unroll
        for (int s = 0; s < KT; s++) ptr[s] = 0;
        int* op = idx + ((size_t)b*npts + qq) * KNN;
        for (int outi = 0; outi <= KNN; outi++) {
            float bestd = INF_F; int besti = 0x7fffffff; int bests = 0;
#pragma unroll
            for (int s = 0; s < KT; s++) {
                if (ptr[s] <= KNN) {
                    float d = msd[tid][s][ptr[s]];
                    int   ii = msi[tid][s][ptr[s]];
                    if (d < bestd || (d == bestd && ii < besti)) {
                        bestd = d; besti = ii; bests = s;
                    }
                }
            }
            ptr[bests]++;
            if (outi > 0) op[outi-1] = besti;
        }
    }
}

// ---------------- conv_surface (+ fused fea0), output layout (node, a, c) ----------------
__global__ void conv_surface_kernel(const float* __restrict__ v, const int* __restrict__ idx,
                                    const float* __restrict__ K0, float* __restrict__ fm0,
                                    float* __restrict__ fea_out) {
    int node = blockIdx.x;
    int t = threadIdx.x;                   // 384 = AA*C0; t = a*C0 + c
    __shared__ float sdir[KNN][3];
    __shared__ float sK0[C0*AA*3];         // raw K0: (c, a, 3)
    __shared__ float sred[AA*C0];

    for (int i = t; i < C0*AA*3; i += blockDim.x) sK0[i] = K0[i];
    if (t < KNN) {
        int m = idx[(size_t)node*KNN + t];
        int b = node / N0;
        const float* pn = v + (size_t)node * 3;
        const float* pm = v + ((size_t)b*N0 + m) * 3;
        float dx = pm[0]-pn[0], dy = pm[1]-pn[1], dz = pm[2]-pn[2];
        float den = sqrtf(dx*dx + dy*dy + dz*dz) + 1e-8f;
        sdir[t][0] = dx/den; sdir[t][1] = dy/den; sdir[t][2] = dz/den;
    }
    __syncthreads();

    int a = t / C0, c = t % C0;
    const float* kv = &sK0[(c*AA + a)*3];
    float kx = kv[0], ky = kv[1], kz = kv[2];
    float m = 0.0f;
#pragma unroll
    for (int k = 0; k < KNN; k++) {
        float d = sdir[k][0]*kx + sdir[k][1]*ky + sdir[k][2]*kz;
        m = fmaxf(m, d);
    }
    fm0[(size_t)node * (C0*AA) + t] = m;   // (node, a, c)
    sred[t] = m;
    __syncthreads();
    if (t < C0) {
        float r = sred[t];                 // a = 0
#pragma unroll
        for (int aa = 1; aa < AA; aa++) r = fmaxf(r, sred[aa*C0 + t]);
        fea_out[node * C0 + t] = r;
    }
}

// ---------------- fused dual GEMM: g = A@Ws, fc = A@Wc + bc; A[M,CIN] row-major ----------------
template<int CIN, int COUT>
__global__ void __launch_bounds__(256)
gemm_kernel(const float* __restrict__ A,
            const float* __restrict__ Ws, const float* __restrict__ Wc,
            const float* __restrict__ bc,
            float* __restrict__ g, float* __restrict__ fc) {
    const int BM = 64, BN = 64, BK = 16;
    __shared__ __align__(16) float As[BK][BM + 4];
    __shared__ __align__(16) float Bs[2][BK][BN];   // [0]=Ws, [1]=Wc

    int tid = threadIdx.x;
    int tm = tid / 16;
    int tn = tid % 16;
    size_t m0 = (size_t)blockIdx.x * BM;
    int n0 = blockIdx.y * BN;

    unsigned long long accS[4][2], accC[4][2];
    {
        float b0 = bc[n0 + tn*4 + 0], b1 = bc[n0 + tn*4 + 1];
        float b2 = bc[n0 + tn*4 + 2], b3 = bc[n0 + tn*4 + 3];
        unsigned long long p0 = pack2(b0, b1), p1 = pack2(b2, b3);
#pragma unroll
        for (int i = 0; i < 4; i++) {
            accS[i][0] = 0ULL; accS[i][1] = 0ULL;
            accC[i][0] = p0;   accC[i][1] = p1;
        }
    }

    int la_m = tid / 4;
    int la_k = (tid % 4) * 4;
    int lb_k = tid / 16;
    int lb_n = (tid % 16) * 4;

    for (int k0 = 0; k0 < CIN; k0 += BK) {
        float4 av = *(const float4*)(A + (m0 + la_m) * CIN + k0 + la_k);
        As[la_k+0][la_m] = av.x;
        As[la_k+1][la_m] = av.y;
        As[la_k+2][la_m] = av.z;
        As[la_k+3][la_m] = av.w;
        *(float4*)(&Bs[0][lb_k][lb_n]) =
            *(const float4*)(Ws + (size_t)(k0 + lb_k) * COUT + n0 + lb_n);
        *(float4*)(&Bs[1][lb_k][lb_n]) =
            *(const float4*)(Wc + (size_t)(k0 + lb_k) * COUT + n0 + lb_n);
        __syncthreads();

#pragma unroll
        for (int kk = 0; kk < BK; kk++) {
            float4 a4 = *(const float4*)(&As[kk][tm*4]);
            ulonglong2 bsv = *(const ulonglong2*)(&Bs[0][kk][tn*4]);
            ulonglong2 bcv = *(const ulonglong2*)(&Bs[1][kk][tn*4]);
            unsigned long long ax;
            ax = pack2(a4.x, a4.x);
            accS[0][0] = fma2(ax, bsv.x, accS[0][0]);
            accS[0][1] = fma2(ax, bsv.y, accS[0][1]);
            accC[0][0] = fma2(ax, bcv.x, accC[0][0]);
            accC[0][1] = fma2(ax, bcv.y, accC[0][1]);
            ax = pack2(a4.y, a4.y);
            accS[1][0] = fma2(ax, bsv.x, accS[1][0]);
            accS[1][1] = fma2(ax, bsv.y, accS[1][1]);
            accC[1][0] = fma2(ax, bcv.x, accC[1][0]);
            accC[1][1] = fma2(ax, bcv.y, accC[1][1]);
            ax = pack2(a4.z, a4.z);
            accS[2][0] = fma2(ax, bsv.x, accS[2][0]);
            accS[2][1] = fma2(ax, bsv.y, accS[2][1]);
            accC[2][0] = fma2(ax, bcv.x, accC[2][0]);
            accC[2][1] = fma2(ax, bcv.y, accC[2][1]);
            ax = pack2(a4.w, a4.w);
            accS[3][0] = fma2(ax, bsv.x, accS[3][0]);
            accS[3][1] = fma2(ax, bsv.y, accS[3][1]);
            accC[3][0] = fma2(ax, bcv.x, accC[3][0]);
            accC[3][1] = fma2(ax, bcv.y, accC[3][1]);
        }
        __syncthreads();
    }

#pragma unroll
    for (int i = 0; i < 4; i++) {
        size_t row = m0 + tm*4 + i;
        ulonglong2 vs; vs.x = accS[i][0]; vs.y = accS[i][1];
        ulonglong2 vc; vc.x = accC[i][0]; vc.y = accC[i][1];
        *(ulonglong2*)(g  + row * COUT + n0 + tn*4) = vs;
        *(ulonglong2*)(fc + row * COUT + n0 + tn*4) = vc;
    }
}

// ---------------- neighbor: out = fc + max_k g[idx_k]*theta_k; layout (node, a, c) ----------------
__global__ void __launch_bounds__(256, 4)
neighbor_kernel(const float* __restrict__ g, const float* __restrict__ fc,
                const float* __restrict__ v, const int* __restrict__ idx,
                const float* __restrict__ dirs,
                float* __restrict__ out, int npts, int cout) {
    int node = blockIdx.x;
    int b = node / npts;
    int t = threadIdx.x;
    __shared__ float sdir[KNN][3];
    __shared__ float sth[KNN][AA];
    __shared__ int   sidx[KNN];
    __shared__ float sdv[AA*3];

    if (t < AA*3) sdv[t] = dirs[t];
    if (t < KNN) {
        int m = idx[(size_t)node*KNN + t];
        sidx[t] = m;
        const float* pn = v + (size_t)node * 3;
        const float* pm = v + ((size_t)b*npts + m) * 3;
        float dx = pm[0]-pn[0], dy = pm[1]-pn[1], dz = pm[2]-pn[2];
        float den = sqrtf(dx*dx + dy*dy + dz*dz) + 1e-8f;
        sdir[t][0] = dx/den; sdir[t][1] = dy/den; sdir[t][2] = dz/den;
    }
    __syncthreads();
    if (t < KNN*AA) {
        int k = t / AA, a = t % AA;
        float d = sdir[k][0]*sdv[a*3+0] + sdir[k][1]*sdv[a*3+1] + sdir[k][2]*sdv[a*3+2];
        sth[k][a] = fmaxf(d, 0.0f);
    }
    __syncthreads();

    int tot = cout * AA;
    int tot4 = tot / 4;
    size_t out_off = (size_t)node * tot;
    for (int q = t; q < tot4; q += blockDim.x) {
        int base = q * 4;
        int a = base / cout;
        float4 m = make_float4(-INF_F, -INF_F, -INF_F, -INF_F);
#pragma unroll 4
        for (int k = 0; k < KNN; k++) {
            const float4 gv = *(const float4*)(g + ((size_t)b*npts + sidx[k])*tot + base);
            float tk = sth[k][a];
            m.x = fmaxf(m.x, gv.x*tk);
            m.y = fmaxf(m.y, gv.y*tk);
            m.z = fmaxf(m.z, gv.z*tk);
            m.w = fmaxf(m.w, gv.w*tk);
        }
        float4 f = *(const float4*)(fc + out_off + base);
        *(float4*)(out + out_off + base) =
            make_float4(f.x+m.x, f.y+m.y, f.z+m.z, f.w+m.w);
    }
}

// ---------------- batchnorm stats stage 1: x is [R, C] row-major; 256 slice-blocks ----------------
__global__ void bn_part_kernel(const float* __restrict__ x, double* __restrict__ part,
                               int C, int R) {
    int slice = blockIdx.x;
    int t = threadIdx.x;
    int rpi = 256 / C;
    int c = t % C;
    int rsub = t / C;
    int RS = R / NSLICE;
    double sm = 0.0, s2 = 0.0;
    for (int r = slice*RS + rsub; r < (slice+1)*RS; r += rpi) {
        float v = x[(size_t)r * C + c];
        sm += (double)v; s2 += (double)v * (double)v;
    }
    __shared__ double sh[256], sh2[256];
    sh[t] = sm; sh2[t] = s2;
    __syncthreads();
    if (t < C) {
        double a = sh[t], b = sh2[t];
        for (int j = t + C; j < 256; j += C) { a += sh[j]; b += sh2[j]; }
        part[(slice*C + t)*2 + 0] = a;
        part[(slice*C + t)*2 + 1] = b;
    }
}

// ---------------- batchnorm stats stage 2 ----------------
__global__ void bn_finalize_kernel(const double* __restrict__ part,
                                   const float* __restrict__ gamma, const float* __restrict__ beta,
                                   float* __restrict__ scale, float* __restrict__ shift,
                                   int C, int npts) {
    int c = threadIdx.x;
    if (c >= C) return;
    double s = 0.0, s2 = 0.0;
    for (int sl = 0; sl < NSLICE; sl++) {
        s  += part[(sl*C + c)*2 + 0];
        s2 += part[(sl*C + c)*2 + 1];
    }
    double cnt = (double)BB * npts * AA;
    double mean = s / cnt;
    double var  = s2 / cnt - mean * mean;
    float sc = gamma[c] * (float)(1.0 / sqrt(var + 1e-5));
    scale[c] = sc;
    shift[c] = beta[c] - (float)mean * sc;
}

// ---------------- fused bn apply + relu + fea; layout (node, a, c) ----------------
__global__ void bn_fea_kernel(float* __restrict__ x,
                              const float* __restrict__ scale, const float* __restrict__ shift,
                              float* __restrict__ out, int C, int total_nc) {
    int i = blockIdx.x * blockDim.x + threadIdx.x;
    if (i >= total_nc) return;
    int node = i / C, c = i % C;
    float sc = scale[c], sh = shift[c];
    size_t base = (size_t)node * AA * C + c;
    float m = 0.0f;
#pragma unroll
    for (int a = 0; a < AA; a++) {
        float v = x[base + a*C] * sc + sh;
        v = fmaxf(v, 0.0f);
        x[base + a*C] = v;
        m = fmaxf(m, v);
    }
    out[i] = m;
}

// ---------------- pool (layout-agnostic: contiguous C*AA chunks) ----------------
__global__ void pool_kernel(const float* __restrict__ v, const float* __restrict__ fm,
                            const int* __restrict__ idx,
                            float* __restrict__ v_out, float* __restrict__ fm_out,
                            int npts, int C) {
    int nsel = npts / 4;
    int bs = blockIdx.x;
    int b = bs / nsel, s = bs % nsel;
    int n = s * 4;
    size_t node = (size_t)b * npts + n;
    int t = threadIdx.x;
    __shared__ int sidx[4];
    if (t < 4) sidx[t] = idx[node*KNN + t];
    if (t < 3) v_out[((size_t)b*nsel + s)*3 + t] = v[node*3 + t];
    __syncthreads();
    int tot = C * AA;
    for (int i = t; i < tot; i += blockDim.x) {
        float m = fm[node*tot + i];
#pragma unroll
        for (int k = 0; k < 4; k++)
            m = fmaxf(m, fm[((size_t)b*npts + sidx[k])*tot + i]);
        fm_out[((size_t)b*nsel + s)*tot + i] = m;
    }
}

// ---------------- fea (no-BN layer 4); layout (node, a, c) ----------------
__global__ void fea_kernel(const float* __restrict__ fm, float* __restrict__ out,
                           int C, int npts) {
    int i = blockIdx.x * blockDim.x + threadIdx.x;
    int total = BB * npts * C;
    if (i >= total) return;
    int node = i / C, c = i % C;
    size_t base = (size_t)node * AA * C + c;
    float m = fm[base];
#pragma unroll
    for (int a = 1; a < AA; a++) m = fmaxf(m, fm[base + a*C]);
    out[i] = m;
}

// ---------------- launch ----------------
extern "C" void kernel_launch(void* const* d_in, const int* in_sizes, int n_in,
                              void* d_out, int out_size) {
    const float* vertices = (const float*)d_in[0];
    const float* K0    = (const float*)d_in[1];
    const float* dirs1 = (const float*)d_in[2];
    const float* Wc1   = (const float*)d_in[3];
    const float* bc1   = (const float*)d_in[4];
    const float* Ws1   = (const float*)d_in[5];
    const float* dirs2 = (const float*)d_in[6];
    const float* Wc2   = (const float*)d_in[7];
    const float* bc2   = (const float*)d_in[8];
    const float* Ws2   = (const float*)d_in[9];
    const float* dirs3 = (const float*)d_in[10];
    const float* Wc3   = (const float*)d_in[11];
    const float* bc3   = (const float*)d_in[12];
    const float* Ws3   = (const float*)d_in[13];
    const float* dirs4 = (const float*)d_in[14];
    const float* Wc4   = (const float*)d_in[15];
    const float* bc4   = (const float*)d_in[16];
    const float* Ws4   = (const float*)d_in[17];
    const float* g1 = (const float*)d_in[18];
    const float* b1 = (const float*)d_in[19];
    const float* g2 = (const float*)d_in[20];
    const float* b2 = (const float*)d_in[21];
    const float* g3 = (const float*)d_in[22];
    const float* b3 = (const float*)d_in[23];
    float* out = (float*)d_out;

    float *fm0, *fm1, *fmp1, *fm2, *fm3, *fmp2, *fm4, *gbuf, *fcbuf, *v1, *v2, *bnscale, *bnshift;
    double *bnpart;
    int *idx0, *idx1, *idx2;
    cudaGetSymbolAddress((void**)&fm0,  d_fm0);
    cudaGetSymbolAddress((void**)&fm1,  d_fm1);
    cudaGetSymbolAddress((void**)&fmp1, d_fmp1);
    cudaGetSymbolAddress((void**)&fm2,  d_fm2);
    cudaGetSymbolAddress((void**)&fm3,  d_fm3);
    cudaGetSymbolAddress((void**)&fmp2, d_fmp2);
    cudaGetSymbolAddress((void**)&fm4,  d_fm4);
    cudaGetSymbolAddress((void**)&gbuf, d_gbuf);
    cudaGetSymbolAddress((void**)&fcbuf,d_fcbuf);
    cudaGetSymbolAddress((void**)&idx0, d_idx0);
    cudaGetSymbolAddress((void**)&idx1, d_idx1);
    cudaGetSymbolAddress((void**)&idx2, d_idx2);
    cudaGetSymbolAddress((void**)&v1,   d_v1);
    cudaGetSymbolAddress((void**)&v2,   d_v2);
    cudaGetSymbolAddress((void**)&bnscale, d_bnscale);
    cudaGetSymbolAddress((void**)&bnshift, d_bnshift);
    cudaGetSymbolAddress((void**)&bnpart,  d_bnpart);

    const size_t off0 = 0;
    const size_t off1 = off0 + (size_t)BB*N0*C0;
    const size_t off2 = off1 + (size_t)BB*N0*C1;
    const size_t off3 = off2 + (size_t)BB*N1*C2;
    const size_t off4 = off3 + (size_t)BB*N1*C3;

    const int M0g = BB*N0*AA;   // 98304
    const int M1g = BB*N1*AA;   // 24576
    const int M2g = BB*N2*AA;   // 6144

    // ---- stage 0 ----
    knn_kernel<<<dim3(N0/QB, BB), 256>>>(vertices, idx0, N0);
    conv_surface_kernel<<<BB*N0, C0*AA>>>(vertices, idx0, K0, fm0, out + off0);

    // ---- layer 1: 32 -> 64 on 4096 ----
    gemm_kernel<C0, C1><<<dim3(M0g/64, C1/64), 256>>>(fm0, Ws1, Wc1, bc1, gbuf, fcbuf);
    neighbor_kernel<<<BB*N0, 256>>>(gbuf, fcbuf, vertices, idx0, dirs1, fm1, N0, C1);
    bn_part_kernel<<<NSLICE, 256>>>(fm1, bnpart, C1, M0g);
    bn_finalize_kernel<<<1, 256>>>(bnpart, g1, b1, bnscale, bnshift, C1, N0);
    bn_fea_kernel<<<(BB*N0*C1 + 255)/256, 256>>>(fm1, bnscale, bnshift, out + off1, C1, BB*N0*C1);

    // ---- pool 1 + knn on 1024 ----
    pool_kernel<<<BB*N1, 256>>>(vertices, fm1, idx0, v1, fmp1, N0, C1);
    knn_kernel<<<dim3(N1/QB, BB), 256>>>(v1, idx1, N1);

    // ---- layer 2: 64 -> 128 on 1024 ----
    gemm_kernel<C1, C2><<<dim3(M1g/64, C2/64), 256>>>(fmp1, Ws2, Wc2, bc2, gbuf, fcbuf);
    neighbor_kernel<<<BB*N1, 256>>>(gbuf, fcbuf, v1, idx1, dirs2, fm2, N1, C2);
    bn_part_kernel<<<NSLICE, 256>>>(fm2, bnpart, C2, M1g);
    bn_finalize_kernel<<<1, 256>>>(bnpart, g2, b2, bnscale, bnshift, C2, N1);
    bn_fea_kernel<<<(BB*N1*C2 + 255)/256, 256>>>(fm2, bnscale, bnshift, out + off2, C2, BB*N1*C2);

    // ---- layer 3: 128 -> 256 on 1024 ----
    gemm_kernel<C2, C3><<<dim3(M1g/64, C3/64), 256>>>(fm2, Ws3, Wc3, bc3, gbuf, fcbuf);
    neighbor_kernel<<<BB*N1, 256>>>(gbuf, fcbuf, v1, idx1, dirs3, fm3, N1, C3);
    bn_part_kernel<<<NSLICE, 256>>>(fm3, bnpart, C3, M1g);
    bn_finalize_kernel<<<1, 256>>>(bnpart, g3, b3, bnscale, bnshift, C3, N1);
    bn_fea_kernel<<<(BB*N1*C3 + 255)/256, 256>>>(fm3, bnscale, bnshift, out + off3, C3, BB*N1*C3);

    // ---- pool 2 + knn on 256 ----
    pool_kernel<<<BB*N2, 256>>>(v1, fm3, idx1, v2, fmp2, N1, C3);
    knn_kernel<<<dim3(N2/QB, BB), 256>>>(v2, idx2, N2);

    // ---- layer 4: 256 -> 512 on 256 (no BN/relu) ----
    gemm_kernel<C3, C4><<<dim3(M2g/64, C4/64), 256>>>(fmp2, Ws4, Wc4, bc4, gbuf, fcbuf);
    neighbor_kernel<<<BB*N2, 256>>>(gbuf, fcbuf, v2, idx2, dirs4, fm4, N2, C4);
    fea_kernel<<<(BB*N2*C4 + 255)/256, 256>>>(fm4, out + off4, C4, N2);
}

// round 16
// speedup vs baseline: 1.0224x; 1.0224x over previous
#include <cuda_runtime.h>
#include <cuda_bf16.h>
#include <math.h>
#include <stdint.h>
#include <stddef.h>

#define BB   2
#define N0   4096
#define N1   1024
#define N2   256
#define KNN  20
#define AA   12

#define C0   32
#define C1   64
#define C2   128
#define C3   256
#define C4   512

#define NSLICE 256

// KNN parallelization
#define KT    8          // threads per query
#define QB    32         // queries per block (KT*QB = 256 threads)
#define KTILE 256        // candidates per tile (all npts divide this or vice versa)

#define INF_F __int_as_float(0x7f800000)

// ---------------- scratch (device globals; no runtime allocation) ----------------
// All feature maps use layout (node, a, c): element (node, a, c) at node*AA*C + a*C + c.
__device__ float d_fm0 [BB*N0*C0*AA];
__device__ float d_fm1 [BB*N0*C1*AA];
__device__ float d_fmp1[BB*N1*C1*AA];
__device__ float d_fm2 [BB*N1*C2*AA];
__device__ float d_fm3 [BB*N1*C3*AA];
__device__ float d_fmp2[BB*N2*C3*AA];
__device__ float d_fm4 [BB*N2*C4*AA];
__device__ float d_gbuf [BB*N0*C1*AA];
__device__ float d_fcbuf[BB*N0*C1*AA];
__device__ int   d_idx0[BB*N0*KNN];
__device__ int   d_idx1[BB*N1*KNN];
__device__ int   d_idx2[BB*N2*KNN];
__device__ float d_v1[BB*N1*3];
__device__ float d_v2[BB*N2*3];
__device__ float d_bnscale[C4];
__device__ float d_bnshift[C4];
__device__ double d_bnpart[NSLICE*C3*2];

// ---------------- packed fp32x2 helpers ----------------
__device__ __forceinline__ unsigned long long pack2(float lo, float hi) {
    unsigned long long r;
    asm("mov.b64 %0, {%1, %2};" : "=l"(r) : "f"(lo), "f"(hi));
    return r;
}
__device__ __forceinline__ void unpack2(float& lo, float& hi, unsigned long long p) {
    asm("mov.b64 {%0, %1}, %2;" : "=f"(lo), "=f"(hi) : "l"(p));
}
__device__ __forceinline__ unsigned long long fma2(unsigned long long a,
                                                   unsigned long long b,
                                                   unsigned long long c) {
    unsigned long long d;
    asm("fma.rn.f32x2 %0, %1, %2, %3;" : "=l"(d) : "l"(a), "l"(b), "l"(c));
    return d;
}
__device__ __forceinline__ unsigned long long add2(unsigned long long a,
                                                   unsigned long long b) {
    unsigned long long d;
    asm("add.rn.f32x2 %0, %1, %2;" : "=l"(d) : "l"(a), "l"(b));
    return d;
}

// ---------------- KNN: 8 threads/query, f32x2-packed scan, register top-21, 8-way merge ----
// dist for candidate pair computed as fma2 chain; per-thread top-21 lists merged with
// lexicographic (dist, idx) order -> exact global top-21 independent of partition.
__global__ void __launch_bounds__(256)
knn_kernel(const float* __restrict__ v, int* __restrict__ idx, int npts) {
    int b = blockIdx.y;
    int tid = threadIdx.x;
    int sub = tid % KT;
    int ql  = tid / KT;
    int q = blockIdx.x * QB + ql;
    const float* vb = v + (size_t)b * npts * 3;

    float qx = vb[q*3+0], qy = vb[q*3+1], qz = vb[q*3+2];
    float qd2 = qx*qx + qy*qy + qz*qz;
    unsigned long long qxm = pack2(-2.0f*qx, -2.0f*qx);
    unsigned long long qym = pack2(-2.0f*qy, -2.0f*qy);
    unsigned long long qzm = pack2(-2.0f*qz, -2.0f*qz);
    unsigned long long qdp = pack2(qd2, qd2);

    float bd[KNN+1];
    int   bi[KNN+1];
#pragma unroll
    for (int i = 0; i <= KNN; i++) { bd[i] = INF_F; bi[i] = -1; }

    // pair-packed candidate tile: spxy[p] = (x0,x1,y0,y1), spzd[p] = (z0,z1,d0,d1)
    __shared__ __align__(16) float spxy[KTILE/2 * 4];
    __shared__ __align__(16) float spzd[KTILE/2 * 4];
    __shared__ float msd[QB][KT][KNN+1];
    __shared__ int   msi[QB][KT][KNN+1];

    for (int tile = 0; tile < npts; tile += KTILE) {
        int j = tile + tid;
        if (j < npts) {
            float x = vb[j*3+0], y = vb[j*3+1], z = vb[j*3+2];
            int p = tid >> 1, h = tid & 1;
            spxy[p*4 + h]     = x;
            spxy[p*4 + 2 + h] = y;
            spzd[p*4 + h]     = z;
            spzd[p*4 + 2 + h] = x*x + y*y + z*z;
        }
        __syncthreads();
        int cnt = npts - tile; if (cnt > KTILE) cnt = KTILE;
        int pairs = cnt >> 1;                        // cnt is always even here
        for (int p = sub; p < pairs; p += KT) {
            ulonglong2 xy = *(const ulonglong2*)(spxy + p*4);   // .x=(x0,x1) .y=(y0,y1)
            ulonglong2 zd = *(const ulonglong2*)(spzd + p*4);   // .x=(z0,z1) .y=(d0,d1)
            unsigned long long acc = add2(zd.y, qdp);
            acc = fma2(zd.x, qzm, acc);
            acc = fma2(xy.y, qym, acc);
            acc = fma2(xy.x, qxm, acc);
            float dlo, dhi;
            unpack2(dlo, dhi, acc);
            int jbase = tile + p*2;
            if (dlo < bd[KNN]) {
#pragma unroll
                for (int i = KNN; i > 0; i--) {
                    bool up = bd[i-1] > dlo;
                    bool pl = bd[i]   > dlo;
                    float nb = up ? bd[i-1] : (pl ? dlo : bd[i]);
                    int   ni = up ? bi[i-1] : (pl ? jbase : bi[i]);
                    bd[i] = nb; bi[i] = ni;
                }
                if (bd[0] > dlo) { bd[0] = dlo; bi[0] = jbase; }
            }
            if (dhi < bd[KNN]) {
                int jh = jbase + 1;
#pragma unroll
                for (int i = KNN; i > 0; i--) {
                    bool up = bd[i-1] > dhi;
                    bool pl = bd[i]   > dhi;
                    float nb = up ? bd[i-1] : (pl ? dhi : bd[i]);
                    int   ni = up ? bi[i-1] : (pl ? jh : bi[i]);
                    bd[i] = nb; bi[i] = ni;
                }
                if (bd[0] > dhi) { bd[0] = dhi; bi[0] = jh; }
            }
        }
        __syncthreads();
    }

    // dump per-thread lists
#pragma unroll
    for (int i = 0; i <= KNN; i++) { msd[ql][sub][i] = bd[i]; msi[ql][sub][i] = bi[i]; }
    __syncthreads();

    // one thread per query: 8-way merge of sorted lists, drop first (self)
    if (tid < QB) {
        int qq = blockIdx.x * QB + tid;
        int ptr[KT];
#pragma unroll
        for (int s = 0; s < KT; s++) ptr[s] = 0;
        int* op = idx + ((size_t)b*npts + qq) * KNN;
        for (int outi = 0; outi <= KNN; outi++) {
            float bestd = INF_F; int besti = 0x7fffffff; int bests = 0;
#pragma unroll
            for (int s = 0; s < KT; s++) {
                if (ptr[s] <= KNN) {
                    float d = msd[tid][s][ptr[s]];
                    int   ii = msi[tid][s][ptr[s]];
                    if (d < bestd || (d == bestd && ii < besti)) {
                        bestd = d; besti = ii; bests = s;
                    }
                }
            }
            ptr[bests]++;
            if (outi > 0) op[outi-1] = besti;
        }
    }
}

// ---------------- conv_surface (+ fused fea0), output layout (node, a, c) ----------------
__global__ void conv_surface_kernel(const float* __restrict__ v, const int* __restrict__ idx,
                                    const float* __restrict__ K0, float* __restrict__ fm0,
                                    float* __restrict__ fea_out) {
    int node = blockIdx.x;
    int t = threadIdx.x;                   // 384 = AA*C0; t = a*C0 + c
    __shared__ float sdir[KNN][3];
    __shared__ float sK0[C0*AA*3];         // raw K0: (c, a, 3)
    __shared__ float sred[AA*C0];

    for (int i = t; i < C0*AA*3; i += blockDim.x) sK0[i] = K0[i];
    if (t < KNN) {
        int m = idx[(size_t)node*KNN + t];
        int b = node / N0;
        const float* pn = v + (size_t)node * 3;
        const float* pm = v + ((size_t)b*N0 + m) * 3;
        float dx = pm[0]-pn[0], dy = pm[1]-pn[1], dz = pm[2]-pn[2];
        float den = sqrtf(dx*dx + dy*dy + dz*dz) + 1e-8f;
        sdir[t][0] = dx/den; sdir[t][1] = dy/den; sdir[t][2] = dz/den;
    }
    __syncthreads();

    int a = t / C0, c = t % C0;
    const float* kv = &sK0[(c*AA + a)*3];
    float kx = kv[0], ky = kv[1], kz = kv[2];
    float m = 0.0f;
#pragma unroll
    for (int k = 0; k < KNN; k++) {
        float d = sdir[k][0]*kx + sdir[k][1]*ky + sdir[k][2]*kz;
        m = fmaxf(m, d);
    }
    fm0[(size_t)node * (C0*AA) + t] = m;   // (node, a, c)
    sred[t] = m;
    __syncthreads();
    if (t < C0) {
        float r = sred[t];                 // a = 0
#pragma unroll
        for (int aa = 1; aa < AA; aa++) r = fmaxf(r, sred[aa*C0 + t]);
        fea_out[node * C0 + t] = r;
    }
}

// ---------------- fused dual GEMM: g = A@Ws, fc = A@Wc + bc; A[M,CIN] row-major ----------------
template<int CIN, int COUT>
__global__ void __launch_bounds__(256)
gemm_kernel(const float* __restrict__ A,
            const float* __restrict__ Ws, const float* __restrict__ Wc,
            const float* __restrict__ bc,
            float* __restrict__ g, float* __restrict__ fc) {
    const int BM = 64, BN = 64, BK = 16;
    __shared__ __align__(16) float As[BK][BM + 4];
    __shared__ __align__(16) float Bs[2][BK][BN];   // [0]=Ws, [1]=Wc

    int tid = threadIdx.x;
    int tm = tid / 16;
    int tn = tid % 16;
    size_t m0 = (size_t)blockIdx.x * BM;
    int n0 = blockIdx.y * BN;

    unsigned long long accS[4][2], accC[4][2];
    {
        float b0 = bc[n0 + tn*4 + 0], b1 = bc[n0 + tn*4 + 1];
        float b2 = bc[n0 + tn*4 + 2], b3 = bc[n0 + tn*4 + 3];
        unsigned long long p0 = pack2(b0, b1), p1 = pack2(b2, b3);
#pragma unroll
        for (int i = 0; i < 4; i++) {
            accS[i][0] = 0ULL; accS[i][1] = 0ULL;
            accC[i][0] = p0;   accC[i][1] = p1;
        }
    }

    int la_m = tid / 4;
    int la_k = (tid % 4) * 4;
    int lb_k = tid / 16;
    int lb_n = (tid % 16) * 4;

    for (int k0 = 0; k0 < CIN; k0 += BK) {
        float4 av = *(const float4*)(A + (m0 + la_m) * CIN + k0 + la_k);
        As[la_k+0][la_m] = av.x;
        As[la_k+1][la_m] = av.y;
        As[la_k+2][la_m] = av.z;
        As[la_k+3][la_m] = av.w;
        *(float4*)(&Bs[0][lb_k][lb_n]) =
            *(const float4*)(Ws + (size_t)(k0 + lb_k) * COUT + n0 + lb_n);
        *(float4*)(&Bs[1][lb_k][lb_n]) =
            *(const float4*)(Wc + (size_t)(k0 + lb_k) * COUT + n0 + lb_n);
        __syncthreads();

#pragma unroll
        for (int kk = 0; kk < BK; kk++) {
            float4 a4 = *(const float4*)(&As[kk][tm*4]);
            ulonglong2 bsv = *(const ulonglong2*)(&Bs[0][kk][tn*4]);
            ulonglong2 bcv = *(const ulonglong2*)(&Bs[1][kk][tn*4]);
            unsigned long long ax;
            ax = pack2(a4.x, a4.x);
            accS[0][0] = fma2(ax, bsv.x, accS[0][0]);
            accS[0][1] = fma2(ax, bsv.y, accS[0][1]);
            accC[0][0] = fma2(ax, bcv.x, accC[0][0]);
            accC[0][1] = fma2(ax, bcv.y, accC[0][1]);
            ax = pack2(a4.y, a4.y);
            accS[1][0] = fma2(ax, bsv.x, accS[1][0]);
            accS[1][1] = fma2(ax, bsv.y, accS[1][1]);
            accC[1][0] = fma2(ax, bcv.x, accC[1][0]);
            accC[1][1] = fma2(ax, bcv.y, accC[1][1]);
            ax = pack2(a4.z, a4.z);
            accS[2][0] = fma2(ax, bsv.x, accS[2][0]);
            accS[2][1] = fma2(ax, bsv.y, accS[2][1]);
            accC[2][0] = fma2(ax, bcv.x, accC[2][0]);
            accC[2][1] = fma2(ax, bcv.y, accC[2][1]);
            ax = pack2(a4.w, a4.w);
            accS[3][0] = fma2(ax, bsv.x, accS[3][0]);
            accS[3][1] = fma2(ax, bsv.y, accS[3][1]);
            accC[3][0] = fma2(ax, bcv.x, accC[3][0]);
            accC[3][1] = fma2(ax, bcv.y, accC[3][1]);
        }
        __syncthreads();
    }

#pragma unroll
    for (int i = 0; i < 4; i++) {
        size_t row = m0 + tm*4 + i;
        ulonglong2 vs; vs.x = accS[i][0]; vs.y = accS[i][1];
        ulonglong2 vc; vc.x = accC[i][0]; vc.y = accC[i][1];
        *(ulonglong2*)(g  + row * COUT + n0 + tn*4) = vs;
        *(ulonglong2*)(fc + row * COUT + n0 + tn*4) = vc;
    }
}

// ---------------- neighbor: out = fc + max_k g[idx_k]*theta_k; layout (node, a, c) ----------------
__global__ void __launch_bounds__(256, 4)
neighbor_kernel(const float* __restrict__ g, const float* __restrict__ fc,
                const float* __restrict__ v, const int* __restrict__ idx,
                const float* __restrict__ dirs,
                float* __restrict__ out, int npts, int cout) {
    int node = blockIdx.x;
    int b = node / npts;
    int t = threadIdx.x;
    __shared__ float sdir[KNN][3];
    __shared__ float sth[KNN][AA];
    __shared__ int   sidx[KNN];
    __shared__ float sdv[AA*3];

    if (t < AA*3) sdv[t] = dirs[t];
    if (t < KNN) {
        int m = idx[(size_t)node*KNN + t];
        sidx[t] = m;
        const float* pn = v + (size_t)node * 3;
        const float* pm = v + ((size_t)b*npts + m) * 3;
        float dx = pm[0]-pn[0], dy = pm[1]-pn[1], dz = pm[2]-pn[2];
        float den = sqrtf(dx*dx + dy*dy + dz*dz) + 1e-8f;
        sdir[t][0] = dx/den; sdir[t][1] = dy/den; sdir[t][2] = dz/den;
    }
    __syncthreads();
    if (t < KNN*AA) {
        int k = t / AA, a = t % AA;
        float d = sdir[k][0]*sdv[a*3+0] + sdir[k][1]*sdv[a*3+1] + sdir[k][2]*sdv[a*3+2];
        sth[k][a] = fmaxf(d, 0.0f);
    }
    __syncthreads();

    int tot = cout * AA;
    int tot4 = tot / 4;
    size_t out_off = (size_t)node * tot;
    for (int q = t; q < tot4; q += blockDim.x) {
        int base = q * 4;
        int a = base / cout;
        float4 m = make_float4(-INF_F, -INF_F, -INF_F, -INF_F);
#pragma unroll 4
        for (int k = 0; k < KNN; k++) {
            const float4 gv = *(const float4*)(g + ((size_t)b*npts + sidx[k])*tot + base);
            float tk = sth[k][a];
            m.x = fmaxf(m.x, gv.x*tk);
            m.y = fmaxf(m.y, gv.y*tk);
            m.z = fmaxf(m.z, gv.z*tk);
            m.w = fmaxf(m.w, gv.w*tk);
        }
        float4 f = *(const float4*)(fc + out_off + base);
        *(float4*)(out + out_off + base) =
            make_float4(f.x+m.x, f.y+m.y, f.z+m.z, f.w+m.w);
    }
}

// ---------------- batchnorm stats stage 1: x is [R, C] row-major; 256 slice-blocks ----------------
__global__ void bn_part_kernel(const float* __restrict__ x, double* __restrict__ part,
                               int C, int R) {
    int slice = blockIdx.x;
    int t = threadIdx.x;
    int rpi = 256 / C;
    int c = t % C;
    int rsub = t / C;
    int RS = R / NSLICE;
    double sm = 0.0, s2 = 0.0;
    for (int r = slice*RS + rsub; r < (slice+1)*RS; r += rpi) {
        float v = x[(size_t)r * C + c];
        sm += (double)v; s2 += (double)v * (double)v;
    }
    __shared__ double sh[256], sh2[256];
    sh[t] = sm; sh2[t] = s2;
    __syncthreads();
    if (t < C) {
        double a = sh[t], b = sh2[t];
        for (int j = t + C; j < 256; j += C) { a += sh[j]; b += sh2[j]; }
        part[(slice*C + t)*2 + 0] = a;
        part[(slice*C + t)*2 + 1] = b;
    }
}

// ---------------- batchnorm stats stage 2 ----------------
__global__ void bn_finalize_kernel(const double* __restrict__ part,
                                   const float* __restrict__ gamma, const float* __restrict__ beta,
                                   float* __restrict__ scale, float* __restrict__ shift,
                                   int C, int npts) {
    int c = threadIdx.x;
    if (c >= C) return;
    double s = 0.0, s2 = 0.0;
    for (int sl = 0; sl < NSLICE; sl++) {
        s  += part[(sl*C + c)*2 + 0];
        s2 += part[(sl*C + c)*2 + 1];
    }
    double cnt = (double)BB * npts * AA;
    double mean = s / cnt;
    double var  = s2 / cnt - mean * mean;
    float sc = gamma[c] * (float)(1.0 / sqrt(var + 1e-5));
    scale[c] = sc;
    shift[c] = beta[c] - (float)mean * sc;
}

// ---------------- fused bn apply + relu + fea; layout (node, a, c) ----------------
__global__ void bn_fea_kernel(float* __restrict__ x,
                              const float* __restrict__ scale, const float* __restrict__ shift,
                              float* __restrict__ out, int C, int total_nc) {
    int i = blockIdx.x * blockDim.x + threadIdx.x;
    if (i >= total_nc) return;
    int node = i / C, c = i % C;
    float sc = scale[c], sh = shift[c];
    size_t base = (size_t)node * AA * C + c;
    float m = 0.0f;
#pragma unroll
    for (int a = 0; a < AA; a++) {
        float v = x[base + a*C] * sc + sh;
        v = fmaxf(v, 0.0f);
        x[base + a*C] = v;
        m = fmaxf(m, v);
    }
    out[i] = m;
}

// ---------------- pool (layout-agnostic: contiguous C*AA chunks) ----------------
__global__ void pool_kernel(const float* __restrict__ v, const float* __restrict__ fm,
                            const int* __restrict__ idx,
                            float* __restrict__ v_out, float* __restrict__ fm_out,
                            int npts, int C) {
    int nsel = npts / 4;
    int bs = blockIdx.x;
    int b = bs / nsel, s = bs % nsel;
    int n = s * 4;
    size_t node = (size_t)b * npts + n;
    int t = threadIdx.x;
    __shared__ int sidx[4];
    if (t < 4) sidx[t] = idx[node*KNN + t];
    if (t < 3) v_out[((size_t)b*nsel + s)*3 + t] = v[node*3 + t];
    __syncthreads();
    int tot = C * AA;
    for (int i = t; i < tot; i += blockDim.x) {
        float m = fm[node*tot + i];
#pragma unroll
        for (int k = 0; k < 4; k++)
            m = fmaxf(m, fm[((size_t)b*npts + sidx[k])*tot + i]);
        fm_out[((size_t)b*nsel + s)*tot + i] = m;
    }
}

// ---------------- fea (no-BN layer 4); layout (node, a, c) ----------------
__global__ void fea_kernel(const float* __restrict__ fm, float* __restrict__ out,
                           int C, int npts) {
    int i = blockIdx.x * blockDim.x + threadIdx.x;
    int total = BB * npts * C;
    if (i >= total) return;
    int node = i / C, c = i % C;
    size_t base = (size_t)node * AA * C + c;
    float m = fm[base];
#pragma unroll
    for (int a = 1; a < AA; a++) m = fmaxf(m, fm[base + a*C]);
    out[i] = m;
}

// ---------------- launch ----------------
extern "C" void kernel_launch(void* const* d_in, const int* in_sizes, int n_in,
                              void* d_out, int out_size) {
    const float* vertices = (const float*)d_in[0];
    const float* K0    = (const float*)d_in[1];
    const float* dirs1 = (const float*)d_in[2];
    const float* Wc1   = (const float*)d_in[3];
    const float* bc1   = (const float*)d_in[4];
    const float* Ws1   = (const float*)d_in[5];
    const float* dirs2 = (const float*)d_in[6];
    const float* Wc2   = (const float*)d_in[7];
    const float* bc2   = (const float*)d_in[8];
    const float* Ws2   = (const float*)d_in[9];
    const float* dirs3 = (const float*)d_in[10];
    const float* Wc3   = (const float*)d_in[11];
    const float* bc3   = (const float*)d_in[12];
    const float* Ws3   = (const float*)d_in[13];
    const float* dirs4 = (const float*)d_in[14];
    const float* Wc4   = (const float*)d_in[15];
    const float* bc4   = (const float*)d_in[16];
    const float* Ws4   = (const float*)d_in[17];
    const float* g1 = (const float*)d_in[18];
    const float* b1 = (const float*)d_in[19];
    const float* g2 = (const float*)d_in[20];
    const float* b2 = (const float*)d_in[21];
    const float* g3 = (const float*)d_in[22];
    const float* b3 = (const float*)d_in[23];
    float* out = (float*)d_out;

    float *fm0, *fm1, *fmp1, *fm2, *fm3, *fmp2, *fm4, *gbuf, *fcbuf, *v1, *v2, *bnscale, *bnshift;
    double *bnpart;
    int *idx0, *idx1, *idx2;
    cudaGetSymbolAddress((void**)&fm0,  d_fm0);
    cudaGetSymbolAddress((void**)&fm1,  d_fm1);
    cudaGetSymbolAddress((void**)&fmp1, d_fmp1);
    cudaGetSymbolAddress((void**)&fm2,  d_fm2);
    cudaGetSymbolAddress((void**)&fm3,  d_fm3);
    cudaGetSymbolAddress((void**)&fmp2, d_fmp2);
    cudaGetSymbolAddress((void**)&fm4,  d_fm4);
    cudaGetSymbolAddress((void**)&gbuf, d_gbuf);
    cudaGetSymbolAddress((void**)&fcbuf,d_fcbuf);
    cudaGetSymbolAddress((void**)&idx0, d_idx0);
    cudaGetSymbolAddress((void**)&idx1, d_idx1);
    cudaGetSymbolAddress((void**)&idx2, d_idx2);
    cudaGetSymbolAddress((void**)&v1,   d_v1);
    cudaGetSymbolAddress((void**)&v2,   d_v2);
    cudaGetSymbolAddress((void**)&bnscale, d_bnscale);
    cudaGetSymbolAddress((void**)&bnshift, d_bnshift);
    cudaGetSymbolAddress((void**)&bnpart,  d_bnpart);

    const size_t off0 = 0;
    const size_t off1 = off0 + (size_t)BB*N0*C0;
    const size_t off2 = off1 + (size_t)BB*N0*C1;
    const size_t off3 = off2 + (size_t)BB*N1*C2;
    const size_t off4 = off3 + (size_t)BB*N1*C3;

    const int M0g = BB*N0*AA;   // 98304
    const int M1g = BB*N1*AA;   // 24576
    const int M2g = BB*N2*AA;   // 6144

    // ---- stage 0 ----
    knn_kernel<<<dim3(N0/QB, BB), 256>>>(vertices, idx0, N0);
    conv_surface_kernel<<<BB*N0, C0*AA>>>(vertices, idx0, K0, fm0, out + off0);

    // ---- layer 1: 32 -> 64 on 4096 ----
    gemm_kernel<C0, C1><<<dim3(M0g/64, C1/64), 256>>>(fm0, Ws1, Wc1, bc1, gbuf, fcbuf);
    neighbor_kernel<<<BB*N0, 256>>>(gbuf, fcbuf, vertices, idx0, dirs1, fm1, N0, C1);
    bn_part_kernel<<<NSLICE, 256>>>(fm1, bnpart, C1, M0g);
    bn_finalize_kernel<<<1, 256>>>(bnpart, g1, b1, bnscale, bnshift, C1, N0);
    bn_fea_kernel<<<(BB*N0*C1 + 255)/256, 256>>>(fm1, bnscale, bnshift, out + off1, C1, BB*N0*C1);

    // ---- pool 1 + knn on 1024 ----
    pool_kernel<<<BB*N1, 256>>>(vertices, fm1, idx0, v1, fmp1, N0, C1);
    knn_kernel<<<dim3(N1/QB, BB), 256>>>(v1, idx1, N1);

    // ---- layer 2: 64 -> 128 on 1024 ----
    gemm_kernel<C1, C2><<<dim3(M1g/64, C2/64), 256>>>(fmp1, Ws2, Wc2, bc2, gbuf, fcbuf);
    neighbor_kernel<<<BB*N1, 256>>>(gbuf, fcbuf, v1, idx1, dirs2, fm2, N1, C2);
    bn_part_kernel<<<NSLICE, 256>>>(fm2, bnpart, C2, M1g);
    bn_finalize_kernel<<<1, 256>>>(bnpart, g2, b2, bnscale, bnshift, C2, N1);
    bn_fea_kernel<<<(BB*N1*C2 + 255)/256, 256>>>(fm2, bnscale, bnshift, out + off2, C2, BB*N1*C2);

    // ---- layer 3: 128 -> 256 on 1024 ----
    gemm_kernel<C2, C3><<<dim3(M1g/64, C3/64), 256>>>(fm2, Ws3, Wc3, bc3, gbuf, fcbuf);
    neighbor_kernel<<<BB*N1, 256>>>(gbuf, fcbuf, v1, idx1, dirs3, fm3, N1, C3);
    bn_part_kernel<<<NSLICE, 256>>>(fm3, bnpart, C3, M1g);
    bn_finalize_kernel<<<1, 256>>>(bnpart, g3, b3, bnscale, bnshift, C3, N1);
    bn_fea_kernel<<<(BB*N1*C3 + 255)/256, 256>>>(fm3, bnscale, bnshift, out + off3, C3, BB*N1*C3);

    // ---- pool 2 + knn on 256 ----
    pool_kernel<<<BB*N2, 256>>>(v1, fm3, idx1, v2, fmp2, N1, C3);
    knn_kernel<<<dim3(N2/QB, BB), 256>>>(v2, idx2, N2);

    // ---- layer 4: 256 -> 512 on 256 (no BN/relu) ----
    gemm_kernel<C3, C4><<<dim3(M2g/64, C4/64), 256>>>(fmp2, Ws4, Wc4, bc4, gbuf, fcbuf);
    neighbor_kernel<<<BB*N2, 256>>>(gbuf, fcbuf, v2, idx2, dirs4, fm4, N2, C4);
    fea_kernel<<<(BB*N2*C4 + 255)/256, 256>>>(fm4, out + off4, C4, N2);
}